// round 14
// baseline (speedup 1.0000x reference)
#include <cuda_runtime.h>
#include <cuda_bf16.h>
#include <cstdint>
#include <math.h>

#define BATCH 512
#define SEQ 256
#define EMBED 384
#define HEAD 64

// Scratch
__device__ float g_Q[BATCH * SEQ * HEAD];
__device__ float g_K[BATCH * SEQ * HEAD];
__device__ float g_V[BATCH * SEQ * HEAD];
__device__ float g_WT[192 * EMBED];   // [n][k], tf32-pre-rounded

// ---------------------------------------------------------------------------
// helpers
// ---------------------------------------------------------------------------
__device__ __forceinline__ float f2tf_f(float x) {
    unsigned r;
    asm("cvt.rna.tf32.f32 %0, %1;" : "=r"(r) : "f"(x));
    return __uint_as_float(r);
}
__device__ __forceinline__ unsigned f2tf(float x) {
    unsigned r;
    asm("cvt.rna.tf32.f32 %0, %1;" : "=r"(r) : "f"(x));
    return r;
}

__device__ __forceinline__ void mma_tf32(float* d, const unsigned* a,
                                         unsigned b0, unsigned b1) {
    asm volatile(
        "mma.sync.aligned.m16n8k8.row.col.f32.tf32.tf32.f32 "
        "{%0,%1,%2,%3}, {%4,%5,%6,%7}, {%8,%9}, {%0,%1,%2,%3};\n"
        : "+f"(d[0]), "+f"(d[1]), "+f"(d[2]), "+f"(d[3])
        : "r"(a[0]), "r"(a[1]), "r"(a[2]), "r"(a[3]), "r"(b0), "r"(b1));
}

__device__ __forceinline__ uint32_t smem_u32(const void* p) {
    uint32_t a;
    asm("{ .reg .u64 t; cvta.to.shared.u64 t, %1; cvt.u32.u64 %0, t; }"
        : "=r"(a) : "l"(p));
    return a;
}

__device__ __forceinline__ void cpa16(uint32_t dst, const void* src) {
    asm volatile("cp.async.cg.shared.global [%0], [%1], 16;"
                 :: "r"(dst), "l"(src) : "memory");
}
#define CPA_COMMIT() asm volatile("cp.async.commit_group;" ::: "memory")
#define CPA_WAIT1()  asm volatile("cp.async.wait_group 1;" ::: "memory")

// ---------------------------------------------------------------------------
// Kernel 0: transpose + tf32-round W -> g_WT[192][384] (n-major, k rows)
// ---------------------------------------------------------------------------
__global__ void wtrans_kernel(const float* __restrict__ Wk,
                              const float* __restrict__ Wq,
                              const float* __restrict__ Wv)
{
    int n = blockIdx.x;        // 0..191
    int k = threadIdx.x;       // 0..383
    const float* src = (n < 64) ? Wk : (n < 128 ? Wq : Wv);
    int nn = n & 63;
    g_WT[n * EMBED + k] = f2tf_f(src[(size_t)k * HEAD + nn]);
}

// ---------------------------------------------------------------------------
// Kernel 1: fused projection GEMM, cp.async double-buffered, 512 threads.
// C[131072 x 192] = X @ [Wk|Wq|Wv].  CTA tile M=128, N=192, k-chunks of 32.
// Warp grid 4(m) x 4(n); warp tile 32 x 48.
// k-slot permutation: slot "t" carries phys k=2t, slot "t+4" carries 2t+1,
// consistently for A and B  -> all fragment loads are contiguous LDS.64.
// B is pre-rounded tf32 (g_WT) -> no CVT on the B path.
// ---------------------------------------------------------------------------
#define XPAD 40    // stride%32==8 -> per-phase banks 8g+2t+c distinct
#define WTPAD 40
#define XS_FLOATS (128 * XPAD)    // 5120
#define WT_FLOATS (192 * WTPAD)   // 7680
#define PROJ_SMEM ((2 * XS_FLOATS + 2 * WT_FLOATS) * 4)   // 102400 B -> 2 CTA/SM

__global__ __launch_bounds__(512, 2)
void proj_kernel(const float* __restrict__ X)
{
    extern __shared__ float sm[];
    float* Xs[2] = {sm, sm + XS_FLOATS};
    float* Wt[2] = {sm + 2 * XS_FLOATS, sm + 2 * XS_FLOATS + WT_FLOATS};

    const int tid  = threadIdx.x;
    const int lane = tid & 31;
    const int warp = tid >> 5;
    const int g = lane >> 2;   // 0..7
    const int t = lane & 3;    // 0..3
    const int wm = warp & 3;   // rows wm*32 .. +31
    const int wn = warp >> 2;  // cols wn*48 .. +47
    const int r0 = blockIdx.x * 128;

    // ---- staging indices ----
    // X tile 128x32 = 1024 float4: 2 per thread
    int xrow[2], xc4[2];
    uint32_t xdst[2][2];
#pragma unroll
    for (int j = 0; j < 2; j++) {
        int idx = tid + j * 512;
        xrow[j] = idx >> 3;
        xc4[j]  = (idx & 7) * 4;
        xdst[0][j] = smem_u32(&Xs[0][xrow[j] * XPAD + xc4[j]]);
        xdst[1][j] = smem_u32(&Xs[1][xrow[j] * XPAD + xc4[j]]);
    }
    // Wt tile 192x32 = 1536 float4: 3 per thread (K-major rows of g_WT)
    int wcol[3], wk4[3];
    uint32_t wdst[2][3];
#pragma unroll
    for (int j = 0; j < 3; j++) {
        int idx = tid + j * 512;
        wcol[j] = idx >> 3;
        wk4[j]  = (idx & 7) * 4;
        wdst[0][j] = smem_u32(&Wt[0][wcol[j] * WTPAD + wk4[j]]);
        wdst[1][j] = smem_u32(&Wt[1][wcol[j] * WTPAD + wk4[j]]);
    }

    float acc[12][4];
#pragma unroll
    for (int f = 0; f < 12; f++)
#pragma unroll
        for (int j = 0; j < 4; j++) acc[f][j] = 0.f;

    // ---- prologue: issue chunk 0 ----
#pragma unroll
    for (int j = 0; j < 2; j++)
        cpa16(xdst[0][j], X + (size_t)(r0 + xrow[j]) * EMBED + xc4[j]);
#pragma unroll
    for (int j = 0; j < 3; j++)
        cpa16(wdst[0][j], g_WT + (size_t)wcol[j] * EMBED + wk4[j]);
    CPA_COMMIT();

#pragma unroll 1
    for (int c = 0; c < 12; c++) {
        const int cb = c & 1;
        if (c < 11) {
            const int nb = 1 - cb;
            const int kk = (c + 1) * 32;
#pragma unroll
            for (int j = 0; j < 2; j++)
                cpa16(xdst[nb][j], X + (size_t)(r0 + xrow[j]) * EMBED + kk + xc4[j]);
#pragma unroll
            for (int j = 0; j < 3; j++)
                cpa16(wdst[nb][j], g_WT + (size_t)wcol[j] * EMBED + kk + wk4[j]);
        }
        CPA_COMMIT();
        CPA_WAIT1();
        __syncthreads();

        const float* Xb = Xs[cb];
        const float* Wb = Wt[cb];
        const int rA = wm * 32 + g;
        const int t2 = 2 * t;
#pragma unroll
        for (int ks = 0; ks < 4; ks++) {
            const int kb = ks * 8;
            // A fragments: phys k (2t, 2t+1) -> slots (t, t+4)
            unsigned a0[4], a1[4];
            float2 v0 = *(const float2*)&Xb[rA * XPAD + kb + t2];
            float2 v1 = *(const float2*)&Xb[(rA + 8) * XPAD + kb + t2];
            float2 v2 = *(const float2*)&Xb[(rA + 16) * XPAD + kb + t2];
            float2 v3 = *(const float2*)&Xb[(rA + 24) * XPAD + kb + t2];
            a0[0] = f2tf(v0.x); a0[2] = f2tf(v0.y);
            a0[1] = f2tf(v1.x); a0[3] = f2tf(v1.y);
            a1[0] = f2tf(v2.x); a1[2] = f2tf(v2.y);
            a1[1] = f2tf(v3.x); a1[3] = f2tf(v3.y);
#pragma unroll
            for (int f = 0; f < 6; f++) {
                int col = wn * 48 + f * 8 + g;
                float2 vb = *(const float2*)&Wb[col * WTPAD + kb + t2];
                unsigned b0 = __float_as_uint(vb.x);   // phys 2t   -> slot t
                unsigned b1 = __float_as_uint(vb.y);   // phys 2t+1 -> slot t+4
                mma_tf32(acc[f], a0, b0, b1);
                mma_tf32(acc[6 + f], a1, b0, b1);
            }
        }
        __syncthreads();
    }

    // ---- epilogue: route columns to K / Q / V ----
#pragma unroll
    for (int mf = 0; mf < 2; mf++) {
#pragma unroll
        for (int f = 0; f < 6; f++) {
            const float* a = acc[mf * 6 + f];
            int n = wn * 48 + f * 8 + 2 * t;
            float* dst;
            int nn;
            if (n < 64)       { dst = g_K; nn = n; }
            else if (n < 128) { dst = g_Q; nn = n - 64; }
            else              { dst = g_V; nn = n - 128; }
            size_t row = (size_t)(r0 + wm * 32 + mf * 16 + g);
            *(float2*)&dst[row * HEAD + nn]       = make_float2(a[0], a[1]);
            *(float2*)&dst[(row + 8) * HEAD + nn] = make_float2(a[2], a[3]);
        }
    }
}

// ---------------------------------------------------------------------------
// Kernel 2: causal attention with KV-halved staging -> 2 CTA/SM.
// (byte-identical to the known-good 73.6us R13 version)
// ---------------------------------------------------------------------------
#define KVPAD 68
#define QPAD  68
#define KVROWS 128
#define ATTN_SMEM ((2 * KVROWS * KVPAD + 8 * 16 * QPAD) * (int)sizeof(float))

__device__ __forceinline__ void attn_chunk(
    const float* __restrict__ Ks, const float* __restrict__ Vs,
    float* __restrict__ Pw, const unsigned qf[8][4], float of[8][4],
    float& m0, float& m1, float& l0, float& l1,
    int bj, bool mask, int rg, int rg8, int cbase, int g, int t)
{
    float s[4][4];
#pragma unroll
    for (int nf = 0; nf < 4; nf++)
#pragma unroll
        for (int e = 0; e < 4; e++) s[nf][e] = 0.f;

#pragma unroll
    for (int ks = 0; ks < 8; ks++) {
        int kb = ks * 8;
#pragma unroll
        for (int nf = 0; nf < 4; nf++) {
            int col = bj * 32 + nf * 8 + g;
            unsigned b0 = __float_as_uint(Ks[col * KVPAD + kb + t]);
            unsigned b1 = __float_as_uint(Ks[col * KVPAD + kb + t + 4]);
            mma_tf32(s[nf], qf[ks], b0, b1);
        }
    }

#pragma unroll
    for (int nf = 0; nf < 4; nf++) {
        int c0 = cbase + nf * 8 + 2 * t;
        s[nf][0] *= 0.125f; s[nf][1] *= 0.125f;
        s[nf][2] *= 0.125f; s[nf][3] *= 0.125f;
        if (mask) {
            if (c0 > rg)      s[nf][0] = -1e30f;
            if (c0 + 1 > rg)  s[nf][1] = -1e30f;
            if (c0 > rg8)     s[nf][2] = -1e30f;
            if (c0 + 1 > rg8) s[nf][3] = -1e30f;
        }
    }

    float nm0 = m0, nm1 = m1;
#pragma unroll
    for (int nf = 0; nf < 4; nf++) {
        nm0 = fmaxf(nm0, fmaxf(s[nf][0], s[nf][1]));
        nm1 = fmaxf(nm1, fmaxf(s[nf][2], s[nf][3]));
    }
    nm0 = fmaxf(nm0, __shfl_xor_sync(0xFFFFFFFFu, nm0, 1));
    nm0 = fmaxf(nm0, __shfl_xor_sync(0xFFFFFFFFu, nm0, 2));
    nm1 = fmaxf(nm1, __shfl_xor_sync(0xFFFFFFFFu, nm1, 1));
    nm1 = fmaxf(nm1, __shfl_xor_sync(0xFFFFFFFFu, nm1, 2));

    float al0 = __expf(m0 - nm0);
    float al1 = __expf(m1 - nm1);

    float ps0 = 0.f, ps1 = 0.f;
#pragma unroll
    for (int nf = 0; nf < 4; nf++) {
        float p0 = __expf(s[nf][0] - nm0);
        float p1 = __expf(s[nf][1] - nm0);
        float p2 = __expf(s[nf][2] - nm1);
        float p3 = __expf(s[nf][3] - nm1);
        ps0 += p0 + p1;
        ps1 += p2 + p3;
        int cl = nf * 8 + 2 * t;
        *(float2*)&Pw[g * QPAD + cl] =
            make_float2(f2tf_f(p0), f2tf_f(p1));
        *(float2*)&Pw[(g + 8) * QPAD + cl] =
            make_float2(f2tf_f(p2), f2tf_f(p3));
    }
    ps0 += __shfl_xor_sync(0xFFFFFFFFu, ps0, 1);
    ps0 += __shfl_xor_sync(0xFFFFFFFFu, ps0, 2);
    ps1 += __shfl_xor_sync(0xFFFFFFFFu, ps1, 1);
    ps1 += __shfl_xor_sync(0xFFFFFFFFu, ps1, 2);

    l0 = l0 * al0 + ps0;
    l1 = l1 * al1 + ps1;
    m0 = nm0; m1 = nm1;

#pragma unroll
    for (int f = 0; f < 8; f++) {
        of[f][0] *= al0; of[f][1] *= al0;
        of[f][2] *= al1; of[f][3] *= al1;
    }
    __syncwarp();

#pragma unroll
    for (int ks = 0; ks < 4; ks++) {
        int kb = ks * 8;
        unsigned pa[4];
        pa[0] = __float_as_uint(Pw[g * QPAD + kb + t]);
        pa[1] = __float_as_uint(Pw[(g + 8) * QPAD + kb + t]);
        pa[2] = __float_as_uint(Pw[g * QPAD + kb + t + 4]);
        pa[3] = __float_as_uint(Pw[(g + 8) * QPAD + kb + t + 4]);
        int vr = bj * 32 + kb;
#pragma unroll
        for (int nf = 0; nf < 8; nf++) {
            int col = nf * 8 + g;
            unsigned b0 = __float_as_uint(Vs[(vr + t) * KVPAD + col]);
            unsigned b1 = __float_as_uint(Vs[(vr + t + 4) * KVPAD + col]);
            mma_tf32(of[nf], pa, b0, b1);
        }
    }
    __syncwarp();
}

__global__ __launch_bounds__(256, 2)
void attn_kernel(float* __restrict__ out)
{
    extern __shared__ float smf[];
    float* Ks = smf;
    float* Vs = Ks + KVROWS * KVPAD;
    float* QP = Vs + KVROWS * KVPAD;

    const int b    = blockIdx.x;
    const int tid  = threadIdx.x;
    const int lane = tid & 31;
    const int warp = tid >> 5;
    const int g = lane >> 2;
    const int t = lane & 3;
    const size_t base = (size_t)b * SEQ * HEAD;

    for (int i = tid; i < KVROWS * HEAD / 4; i += 256) {
        int s = i >> 4;
        int d = (i & 15) * 4;
        float4 k4 = *(const float4*)&g_K[base + (size_t)s * HEAD + d];
        float4 v4 = *(const float4*)&g_V[base + (size_t)s * HEAD + d];
        k4.x = f2tf_f(k4.x); k4.y = f2tf_f(k4.y);
        k4.z = f2tf_f(k4.z); k4.w = f2tf_f(k4.w);
        v4.x = f2tf_f(v4.x); v4.y = f2tf_f(v4.y);
        v4.z = f2tf_f(v4.z); v4.w = f2tf_f(v4.w);
        *(float4*)&Ks[s * KVPAD + d] = k4;
        *(float4*)&Vs[s * KVPAD + d] = v4;
    }
    __syncthreads();

    float* Qw = QP + warp * 16 * QPAD;
    unsigned qf[8][4];
    float of[8][4];
    float m0, m1, l0, l1;

    // ===== tile A = warp =====
    {
        const int qr0 = warp * 16;
#pragma unroll
        for (int i = 0; i < 8; i++) {
            int idx = lane + i * 32;
            int row = idx >> 4;
            int c4  = (idx & 15) * 4;
            float4 q4 = *(const float4*)&g_Q[base + (size_t)(qr0 + row) * HEAD + c4];
            q4.x = f2tf_f(q4.x); q4.y = f2tf_f(q4.y);
            q4.z = f2tf_f(q4.z); q4.w = f2tf_f(q4.w);
            *(float4*)&Qw[row * QPAD + c4] = q4;
        }
        __syncwarp();
#pragma unroll
        for (int ks = 0; ks < 8; ks++) {
            int kb = ks * 8;
            qf[ks][0] = __float_as_uint(Qw[g * QPAD + kb + t]);
            qf[ks][1] = __float_as_uint(Qw[(g + 8) * QPAD + kb + t]);
            qf[ks][2] = __float_as_uint(Qw[g * QPAD + kb + t + 4]);
            qf[ks][3] = __float_as_uint(Qw[(g + 8) * QPAD + kb + t + 4]);
        }
        __syncwarp();

#pragma unroll
        for (int f = 0; f < 8; f++)
#pragma unroll
            for (int j = 0; j < 4; j++) of[f][j] = 0.f;
        m0 = -1e30f; m1 = -1e30f; l0 = 0.f; l1 = 0.f;
        const int rg = qr0 + g, rg8 = rg + 8;
        const int jmax = (qr0 + 15) >> 5;

        for (int j = 0; j <= jmax; j++)
            attn_chunk(Ks, Vs, Qw, qf, of, m0, m1, l0, l1,
                       j, j == jmax, rg, rg8, j * 32, g, t);

        float inv0 = 1.f / l0, inv1 = 1.f / l1;
#pragma unroll
        for (int nf = 0; nf < 8; nf++) {
            int col = nf * 8 + 2 * t;
            size_t row = (size_t)(qr0 + g);
            *(float2*)&out[base + row * HEAD + col] =
                make_float2(of[nf][0] * inv0, of[nf][1] * inv0);
            *(float2*)&out[base + (row + 8) * HEAD + col] =
                make_float2(of[nf][2] * inv1, of[nf][3] * inv1);
        }
        __syncwarp();
    }

    // ===== tile B = 15-warp: chunks 0..3 vs half 0 =====
    const int qr0b = (15 - warp) * 16;
    {
#pragma unroll
        for (int i = 0; i < 8; i++) {
            int idx = lane + i * 32;
            int row = idx >> 4;
            int c4  = (idx & 15) * 4;
            float4 q4 = *(const float4*)&g_Q[base + (size_t)(qr0b + row) * HEAD + c4];
            q4.x = f2tf_f(q4.x); q4.y = f2tf_f(q4.y);
            q4.z = f2tf_f(q4.z); q4.w = f2tf_f(q4.w);
            *(float4*)&Qw[row * QPAD + c4] = q4;
        }
        __syncwarp();
#pragma unroll
        for (int ks = 0; ks < 8; ks++) {
            int kb = ks * 8;
            qf[ks][0] = __float_as_uint(Qw[g * QPAD + kb + t]);
            qf[ks][1] = __float_as_uint(Qw[(g + 8) * QPAD + kb + t]);
            qf[ks][2] = __float_as_uint(Qw[g * QPAD + kb + t + 4]);
            qf[ks][3] = __float_as_uint(Qw[(g + 8) * QPAD + kb + t + 4]);
        }
        __syncwarp();

#pragma unroll
        for (int f = 0; f < 8; f++)
#pragma unroll
            for (int j = 0; j < 4; j++) of[f][j] = 0.f;
        m0 = -1e30f; m1 = -1e30f; l0 = 0.f; l1 = 0.f;
        const int rg = qr0b + g, rg8 = rg + 8;

        for (int j = 0; j < 4; j++)
            attn_chunk(Ks, Vs, Qw, qf, of, m0, m1, l0, l1,
                       j, false, rg, rg8, j * 32, g, t);
    }

    __syncthreads();
    for (int i = tid; i < KVROWS * HEAD / 4; i += 256) {
        int s = i >> 4;
        int d = (i & 15) * 4;
        float4 k4 = *(const float4*)&g_K[base + (size_t)(s + 128) * HEAD + d];
        float4 v4 = *(const float4*)&g_V[base + (size_t)(s + 128) * HEAD + d];
        k4.x = f2tf_f(k4.x); k4.y = f2tf_f(k4.y);
        k4.z = f2tf_f(k4.z); k4.w = f2tf_f(k4.w);
        v4.x = f2tf_f(v4.x); v4.y = f2tf_f(v4.y);
        v4.z = f2tf_f(v4.z); v4.w = f2tf_f(v4.w);
        *(float4*)&Ks[s * KVPAD + d] = k4;
        *(float4*)&Vs[s * KVPAD + d] = v4;
    }
    __syncthreads();

    {
        const int rg = qr0b + g, rg8 = rg + 8;
        const int jmax = (qr0b + 15) >> 5;
        for (int j = 4; j <= jmax; j++)
            attn_chunk(Ks, Vs, Qw, qf, of, m0, m1, l0, l1,
                       j - 4, j == jmax, rg, rg8, j * 32, g, t);

        float inv0 = 1.f / l0, inv1 = 1.f / l1;
#pragma unroll
        for (int nf = 0; nf < 8; nf++) {
            int col = nf * 8 + 2 * t;
            size_t row = (size_t)(qr0b + g);
            *(float2*)&out[base + row * HEAD + col] =
                make_float2(of[nf][0] * inv0, of[nf][1] * inv0);
            *(float2*)&out[base + (row + 8) * HEAD + col] =
                make_float2(of[nf][2] * inv1, of[nf][3] * inv1);
        }
    }
}

// ---------------------------------------------------------------------------
extern "C" void kernel_launch(void* const* d_in, const int* in_sizes, int n_in,
                              void* d_out, int out_size)
{
    const float* X  = (const float*)d_in[0];
    const float* Wk = (const float*)d_in[1];
    const float* Wq = (const float*)d_in[2];
    const float* Wv = (const float*)d_in[3];
    float* out = (float*)d_out;

    static bool attr_set = false;
    if (!attr_set) {
        cudaFuncSetAttribute(proj_kernel,
                             cudaFuncAttributeMaxDynamicSharedMemorySize,
                             PROJ_SMEM);
        cudaFuncSetAttribute(attn_kernel,
                             cudaFuncAttributeMaxDynamicSharedMemorySize,
                             ATTN_SMEM);
        attr_set = true;
    }

    wtrans_kernel<<<192, 384>>>(Wk, Wq, Wv);
    proj_kernel<<<(BATCH * SEQ) / 128, 512, PROJ_SMEM>>>(X);
    attn_kernel<<<BATCH, 256, ATTN_SMEM>>>(out);
}

// round 16
// speedup vs baseline: 2.5122x; 2.5122x over previous
#include <cuda_runtime.h>
#include <cuda_bf16.h>
#include <cstdint>
#include <math.h>

#define BATCH 512
#define SEQ 256
#define EMBED 384
#define HEAD 64

// Scratch
__device__ float g_Q[BATCH * SEQ * HEAD];
__device__ float g_K[BATCH * SEQ * HEAD];
__device__ float g_V[BATCH * SEQ * HEAD];
__device__ float g_WT[192 * EMBED];   // [n][k], tf32-pre-rounded

// ---------------------------------------------------------------------------
// helpers
// ---------------------------------------------------------------------------
__device__ __forceinline__ float f2tf_f(float x) {
    unsigned r;
    asm("cvt.rna.tf32.f32 %0, %1;" : "=r"(r) : "f"(x));
    return __uint_as_float(r);
}
__device__ __forceinline__ unsigned f2tf(float x) {
    unsigned r;
    asm("cvt.rna.tf32.f32 %0, %1;" : "=r"(r) : "f"(x));
    return r;
}

__device__ __forceinline__ void mma_tf32(float* d, const unsigned* a,
                                         unsigned b0, unsigned b1) {
    asm volatile(
        "mma.sync.aligned.m16n8k8.row.col.f32.tf32.tf32.f32 "
        "{%0,%1,%2,%3}, {%4,%5,%6,%7}, {%8,%9}, {%0,%1,%2,%3};\n"
        : "+f"(d[0]), "+f"(d[1]), "+f"(d[2]), "+f"(d[3])
        : "r"(a[0]), "r"(a[1]), "r"(a[2]), "r"(a[3]), "r"(b0), "r"(b1));
}

__device__ __forceinline__ uint32_t smem_u32(const void* p) {
    uint32_t a;
    asm("{ .reg .u64 t; cvta.to.shared.u64 t, %1; cvt.u32.u64 %0, t; }"
        : "=r"(a) : "l"(p));
    return a;
}

__device__ __forceinline__ void cpa16(uint32_t dst, const void* src) {
    asm volatile("cp.async.cg.shared.global [%0], [%1], 16;"
                 :: "r"(dst), "l"(src) : "memory");
}
#define CPA_COMMIT() asm volatile("cp.async.commit_group;" ::: "memory")
#define CPA_WAIT1()  asm volatile("cp.async.wait_group 1;" ::: "memory")

// ---------------------------------------------------------------------------
// Kernel 0: transpose + tf32-round W -> g_WT[192][384] (n-major, k rows)
// ---------------------------------------------------------------------------
__global__ void wtrans_kernel(const float* __restrict__ Wk,
                              const float* __restrict__ Wq,
                              const float* __restrict__ Wv)
{
    int n = blockIdx.x;        // 0..191
    int k = threadIdx.x;       // 0..383
    const float* src = (n < 64) ? Wk : (n < 128 ? Wq : Wv);
    int nn = n & 63;
    g_WT[n * EMBED + k] = f2tf_f(src[(size_t)k * HEAD + nn]);
}

// ---------------------------------------------------------------------------
// Kernel 1: fused projection GEMM, cp.async double-buffered, 512 threads.
// C[131072 x 192] = X @ [Wk|Wq|Wv].  CTA tile M=128, N=192, k-chunks of 32.
// Warp grid 4(m) x 4(n); warp tile 32 x 48.
// k-slot permutation: slot "t" carries phys k=2t, slot "t+4" carries 2t+1,
// consistently for A and B -> all fragment loads are contiguous LDS.64.
// B pre-rounded tf32 (g_WT) -> no CVT on the B path.
// launch_bounds (512,1): do NOT cap regs (R14's (512,2) forced 64 regs ->
// accumulator spills -> 3x slowdown).
// ---------------------------------------------------------------------------
#define XPAD 40    // stride%32==8 -> per-phase banks 8g+2t+c distinct
#define WTPAD 40
#define XS_FLOATS (128 * XPAD)    // 5120
#define WT_FLOATS (192 * WTPAD)   // 7680
#define PROJ_SMEM ((2 * XS_FLOATS + 2 * WT_FLOATS) * 4)   // 102400 B

__global__ __launch_bounds__(512, 1)
void proj_kernel(const float* __restrict__ X)
{
    extern __shared__ float sm[];
    float* Xs[2] = {sm, sm + XS_FLOATS};
    float* Wt[2] = {sm + 2 * XS_FLOATS, sm + 2 * XS_FLOATS + WT_FLOATS};

    const int tid  = threadIdx.x;
    const int lane = tid & 31;
    const int warp = tid >> 5;
    const int g = lane >> 2;   // 0..7
    const int t = lane & 3;    // 0..3
    const int wm = warp & 3;   // rows wm*32 .. +31
    const int wn = warp >> 2;  // cols wn*48 .. +47
    const int r0 = blockIdx.x * 128;

    // ---- staging indices ----
    int xrow[2], xc4[2];
    uint32_t xdst[2][2];
#pragma unroll
    for (int j = 0; j < 2; j++) {
        int idx = tid + j * 512;
        xrow[j] = idx >> 3;
        xc4[j]  = (idx & 7) * 4;
        xdst[0][j] = smem_u32(&Xs[0][xrow[j] * XPAD + xc4[j]]);
        xdst[1][j] = smem_u32(&Xs[1][xrow[j] * XPAD + xc4[j]]);
    }
    int wcol[3], wk4[3];
    uint32_t wdst[2][3];
#pragma unroll
    for (int j = 0; j < 3; j++) {
        int idx = tid + j * 512;
        wcol[j] = idx >> 3;
        wk4[j]  = (idx & 7) * 4;
        wdst[0][j] = smem_u32(&Wt[0][wcol[j] * WTPAD + wk4[j]]);
        wdst[1][j] = smem_u32(&Wt[1][wcol[j] * WTPAD + wk4[j]]);
    }

    float acc[12][4];
#pragma unroll
    for (int f = 0; f < 12; f++)
#pragma unroll
        for (int j = 0; j < 4; j++) acc[f][j] = 0.f;

    // ---- prologue: issue chunk 0 ----
#pragma unroll
    for (int j = 0; j < 2; j++)
        cpa16(xdst[0][j], X + (size_t)(r0 + xrow[j]) * EMBED + xc4[j]);
#pragma unroll
    for (int j = 0; j < 3; j++)
        cpa16(wdst[0][j], g_WT + (size_t)wcol[j] * EMBED + wk4[j]);
    CPA_COMMIT();

#pragma unroll 1
    for (int c = 0; c < 12; c++) {
        const int cb = c & 1;
        if (c < 11) {
            const int nb = 1 - cb;
            const int kk = (c + 1) * 32;
#pragma unroll
            for (int j = 0; j < 2; j++)
                cpa16(xdst[nb][j], X + (size_t)(r0 + xrow[j]) * EMBED + kk + xc4[j]);
#pragma unroll
            for (int j = 0; j < 3; j++)
                cpa16(wdst[nb][j], g_WT + (size_t)wcol[j] * EMBED + kk + wk4[j]);
        }
        CPA_COMMIT();
        CPA_WAIT1();
        __syncthreads();

        const float* Xb = Xs[cb];
        const float* Wb = Wt[cb];
        const int rA = wm * 32 + g;
        const int t2 = 2 * t;
#pragma unroll
        for (int ks = 0; ks < 4; ks++) {
            const int kb = ks * 8;
            unsigned a0[4], a1[4];
            float2 v0 = *(const float2*)&Xb[rA * XPAD + kb + t2];
            float2 v1 = *(const float2*)&Xb[(rA + 8) * XPAD + kb + t2];
            float2 v2 = *(const float2*)&Xb[(rA + 16) * XPAD + kb + t2];
            float2 v3 = *(const float2*)&Xb[(rA + 24) * XPAD + kb + t2];
            a0[0] = f2tf(v0.x); a0[2] = f2tf(v0.y);
            a0[1] = f2tf(v1.x); a0[3] = f2tf(v1.y);
            a1[0] = f2tf(v2.x); a1[2] = f2tf(v2.y);
            a1[1] = f2tf(v3.x); a1[3] = f2tf(v3.y);
#pragma unroll
            for (int f = 0; f < 6; f++) {
                int col = wn * 48 + f * 8 + g;
                float2 vb = *(const float2*)&Wb[col * WTPAD + kb + t2];
                unsigned b0 = __float_as_uint(vb.x);
                unsigned b1 = __float_as_uint(vb.y);
                mma_tf32(acc[f], a0, b0, b1);
                mma_tf32(acc[6 + f], a1, b0, b1);
            }
        }
        __syncthreads();
    }

    // ---- epilogue: route columns to K / Q / V ----
#pragma unroll
    for (int mf = 0; mf < 2; mf++) {
#pragma unroll
        for (int f = 0; f < 6; f++) {
            const float* a = acc[mf * 6 + f];
            int n = wn * 48 + f * 8 + 2 * t;
            float* dst;
            int nn;
            if (n < 64)       { dst = g_K; nn = n; }
            else if (n < 128) { dst = g_Q; nn = n - 64; }
            else              { dst = g_V; nn = n - 128; }
            size_t row = (size_t)(r0 + wm * 32 + mf * 16 + g);
            *(float2*)&dst[row * HEAD + nn]       = make_float2(a[0], a[1]);
            *(float2*)&dst[(row + 8) * HEAD + nn] = make_float2(a[2], a[3]);
        }
    }
}

// ---------------------------------------------------------------------------
// Kernel 2: causal attention with KV-halved staging -> 2 CTA/SM.
// (byte-identical to the known-good 73.6us R13 version)
// ---------------------------------------------------------------------------
#define KVPAD 68
#define QPAD  68
#define KVROWS 128
#define ATTN_SMEM ((2 * KVROWS * KVPAD + 8 * 16 * QPAD) * (int)sizeof(float))

__device__ __forceinline__ void attn_chunk(
    const float* __restrict__ Ks, const float* __restrict__ Vs,
    float* __restrict__ Pw, const unsigned qf[8][4], float of[8][4],
    float& m0, float& m1, float& l0, float& l1,
    int bj, bool mask, int rg, int rg8, int cbase, int g, int t)
{
    float s[4][4];
#pragma unroll
    for (int nf = 0; nf < 4; nf++)
#pragma unroll
        for (int e = 0; e < 4; e++) s[nf][e] = 0.f;

#pragma unroll
    for (int ks = 0; ks < 8; ks++) {
        int kb = ks * 8;
#pragma unroll
        for (int nf = 0; nf < 4; nf++) {
            int col = bj * 32 + nf * 8 + g;
            unsigned b0 = __float_as_uint(Ks[col * KVPAD + kb + t]);
            unsigned b1 = __float_as_uint(Ks[col * KVPAD + kb + t + 4]);
            mma_tf32(s[nf], qf[ks], b0, b1);
        }
    }

#pragma unroll
    for (int nf = 0; nf < 4; nf++) {
        int c0 = cbase + nf * 8 + 2 * t;
        s[nf][0] *= 0.125f; s[nf][1] *= 0.125f;
        s[nf][2] *= 0.125f; s[nf][3] *= 0.125f;
        if (mask) {
            if (c0 > rg)      s[nf][0] = -1e30f;
            if (c0 + 1 > rg)  s[nf][1] = -1e30f;
            if (c0 > rg8)     s[nf][2] = -1e30f;
            if (c0 + 1 > rg8) s[nf][3] = -1e30f;
        }
    }

    float nm0 = m0, nm1 = m1;
#pragma unroll
    for (int nf = 0; nf < 4; nf++) {
        nm0 = fmaxf(nm0, fmaxf(s[nf][0], s[nf][1]));
        nm1 = fmaxf(nm1, fmaxf(s[nf][2], s[nf][3]));
    }
    nm0 = fmaxf(nm0, __shfl_xor_sync(0xFFFFFFFFu, nm0, 1));
    nm0 = fmaxf(nm0, __shfl_xor_sync(0xFFFFFFFFu, nm0, 2));
    nm1 = fmaxf(nm1, __shfl_xor_sync(0xFFFFFFFFu, nm1, 1));
    nm1 = fmaxf(nm1, __shfl_xor_sync(0xFFFFFFFFu, nm1, 2));

    float al0 = __expf(m0 - nm0);
    float al1 = __expf(m1 - nm1);

    float ps0 = 0.f, ps1 = 0.f;
#pragma unroll
    for (int nf = 0; nf < 4; nf++) {
        float p0 = __expf(s[nf][0] - nm0);
        float p1 = __expf(s[nf][1] - nm0);
        float p2 = __expf(s[nf][2] - nm1);
        float p3 = __expf(s[nf][3] - nm1);
        ps0 += p0 + p1;
        ps1 += p2 + p3;
        int cl = nf * 8 + 2 * t;
        *(float2*)&Pw[g * QPAD + cl] =
            make_float2(f2tf_f(p0), f2tf_f(p1));
        *(float2*)&Pw[(g + 8) * QPAD + cl] =
            make_float2(f2tf_f(p2), f2tf_f(p3));
    }
    ps0 += __shfl_xor_sync(0xFFFFFFFFu, ps0, 1);
    ps0 += __shfl_xor_sync(0xFFFFFFFFu, ps0, 2);
    ps1 += __shfl_xor_sync(0xFFFFFFFFu, ps1, 1);
    ps1 += __shfl_xor_sync(0xFFFFFFFFu, ps1, 2);

    l0 = l0 * al0 + ps0;
    l1 = l1 * al1 + ps1;
    m0 = nm0; m1 = nm1;

#pragma unroll
    for (int f = 0; f < 8; f++) {
        of[f][0] *= al0; of[f][1] *= al0;
        of[f][2] *= al1; of[f][3] *= al1;
    }
    __syncwarp();

#pragma unroll
    for (int ks = 0; ks < 4; ks++) {
        int kb = ks * 8;
        unsigned pa[4];
        pa[0] = __float_as_uint(Pw[g * QPAD + kb + t]);
        pa[1] = __float_as_uint(Pw[(g + 8) * QPAD + kb + t]);
        pa[2] = __float_as_uint(Pw[g * QPAD + kb + t + 4]);
        pa[3] = __float_as_uint(Pw[(g + 8) * QPAD + kb + t + 4]);
        int vr = bj * 32 + kb;
#pragma unroll
        for (int nf = 0; nf < 8; nf++) {
            int col = nf * 8 + g;
            unsigned b0 = __float_as_uint(Vs[(vr + t) * KVPAD + col]);
            unsigned b1 = __float_as_uint(Vs[(vr + t + 4) * KVPAD + col]);
            mma_tf32(of[nf], pa, b0, b1);
        }
    }
    __syncwarp();
}

__global__ __launch_bounds__(256, 2)
void attn_kernel(float* __restrict__ out)
{
    extern __shared__ float smf[];
    float* Ks = smf;
    float* Vs = Ks + KVROWS * KVPAD;
    float* QP = Vs + KVROWS * KVPAD;

    const int b    = blockIdx.x;
    const int tid  = threadIdx.x;
    const int lane = tid & 31;
    const int warp = tid >> 5;
    const int g = lane >> 2;
    const int t = lane & 3;
    const size_t base = (size_t)b * SEQ * HEAD;

    for (int i = tid; i < KVROWS * HEAD / 4; i += 256) {
        int s = i >> 4;
        int d = (i & 15) * 4;
        float4 k4 = *(const float4*)&g_K[base + (size_t)s * HEAD + d];
        float4 v4 = *(const float4*)&g_V[base + (size_t)s * HEAD + d];
        k4.x = f2tf_f(k4.x); k4.y = f2tf_f(k4.y);
        k4.z = f2tf_f(k4.z); k4.w = f2tf_f(k4.w);
        v4.x = f2tf_f(v4.x); v4.y = f2tf_f(v4.y);
        v4.z = f2tf_f(v4.z); v4.w = f2tf_f(v4.w);
        *(float4*)&Ks[s * KVPAD + d] = k4;
        *(float4*)&Vs[s * KVPAD + d] = v4;
    }
    __syncthreads();

    float* Qw = QP + warp * 16 * QPAD;
    unsigned qf[8][4];
    float of[8][4];
    float m0, m1, l0, l1;

    // ===== tile A = warp =====
    {
        const int qr0 = warp * 16;
#pragma unroll
        for (int i = 0; i < 8; i++) {
            int idx = lane + i * 32;
            int row = idx >> 4;
            int c4  = (idx & 15) * 4;
            float4 q4 = *(const float4*)&g_Q[base + (size_t)(qr0 + row) * HEAD + c4];
            q4.x = f2tf_f(q4.x); q4.y = f2tf_f(q4.y);
            q4.z = f2tf_f(q4.z); q4.w = f2tf_f(q4.w);
            *(float4*)&Qw[row * QPAD + c4] = q4;
        }
        __syncwarp();
#pragma unroll
        for (int ks = 0; ks < 8; ks++) {
            int kb = ks * 8;
            qf[ks][0] = __float_as_uint(Qw[g * QPAD + kb + t]);
            qf[ks][1] = __float_as_uint(Qw[(g + 8) * QPAD + kb + t]);
            qf[ks][2] = __float_as_uint(Qw[g * QPAD + kb + t + 4]);
            qf[ks][3] = __float_as_uint(Qw[(g + 8) * QPAD + kb + t + 4]);
        }
        __syncwarp();

#pragma unroll
        for (int f = 0; f < 8; f++)
#pragma unroll
            for (int j = 0; j < 4; j++) of[f][j] = 0.f;
        m0 = -1e30f; m1 = -1e30f; l0 = 0.f; l1 = 0.f;
        const int rg = qr0 + g, rg8 = rg + 8;
        const int jmax = (qr0 + 15) >> 5;

        for (int j = 0; j <= jmax; j++)
            attn_chunk(Ks, Vs, Qw, qf, of, m0, m1, l0, l1,
                       j, j == jmax, rg, rg8, j * 32, g, t);

        float inv0 = 1.f / l0, inv1 = 1.f / l1;
#pragma unroll
        for (int nf = 0; nf < 8; nf++) {
            int col = nf * 8 + 2 * t;
            size_t row = (size_t)(qr0 + g);
            *(float2*)&out[base + row * HEAD + col] =
                make_float2(of[nf][0] * inv0, of[nf][1] * inv0);
            *(float2*)&out[base + (row + 8) * HEAD + col] =
                make_float2(of[nf][2] * inv1, of[nf][3] * inv1);
        }
        __syncwarp();
    }

    // ===== tile B = 15-warp: chunks 0..3 vs half 0 =====
    const int qr0b = (15 - warp) * 16;
    {
#pragma unroll
        for (int i = 0; i < 8; i++) {
            int idx = lane + i * 32;
            int row = idx >> 4;
            int c4  = (idx & 15) * 4;
            float4 q4 = *(const float4*)&g_Q[base + (size_t)(qr0b + row) * HEAD + c4];
            q4.x = f2tf_f(q4.x); q4.y = f2tf_f(q4.y);
            q4.z = f2tf_f(q4.z); q4.w = f2tf_f(q4.w);
            *(float4*)&Qw[row * QPAD + c4] = q4;
        }
        __syncwarp();
#pragma unroll
        for (int ks = 0; ks < 8; ks++) {
            int kb = ks * 8;
            qf[ks][0] = __float_as_uint(Qw[g * QPAD + kb + t]);
            qf[ks][1] = __float_as_uint(Qw[(g + 8) * QPAD + kb + t]);
            qf[ks][2] = __float_as_uint(Qw[g * QPAD + kb + t + 4]);
            qf[ks][3] = __float_as_uint(Qw[(g + 8) * QPAD + kb + t + 4]);
        }
        __syncwarp();

#pragma unroll
        for (int f = 0; f < 8; f++)
#pragma unroll
            for (int j = 0; j < 4; j++) of[f][j] = 0.f;
        m0 = -1e30f; m1 = -1e30f; l0 = 0.f; l1 = 0.f;
        const int rg = qr0b + g, rg8 = rg + 8;

        for (int j = 0; j < 4; j++)
            attn_chunk(Ks, Vs, Qw, qf, of, m0, m1, l0, l1,
                       j, false, rg, rg8, j * 32, g, t);
    }

    __syncthreads();
    for (int i = tid; i < KVROWS * HEAD / 4; i += 256) {
        int s = i >> 4;
        int d = (i & 15) * 4;
        float4 k4 = *(const float4*)&g_K[base + (size_t)(s + 128) * HEAD + d];
        float4 v4 = *(const float4*)&g_V[base + (size_t)(s + 128) * HEAD + d];
        k4.x = f2tf_f(k4.x); k4.y = f2tf_f(k4.y);
        k4.z = f2tf_f(k4.z); k4.w = f2tf_f(k4.w);
        v4.x = f2tf_f(v4.x); v4.y = f2tf_f(v4.y);
        v4.z = f2tf_f(v4.z); v4.w = f2tf_f(v4.w);
        *(float4*)&Ks[s * KVPAD + d] = k4;
        *(float4*)&Vs[s * KVPAD + d] = v4;
    }
    __syncthreads();

    {
        const int rg = qr0b + g, rg8 = rg + 8;
        const int jmax = (qr0b + 15) >> 5;
        for (int j = 4; j <= jmax; j++)
            attn_chunk(Ks, Vs, Qw, qf, of, m0, m1, l0, l1,
                       j - 4, j == jmax, rg, rg8, j * 32, g, t);

        float inv0 = 1.f / l0, inv1 = 1.f / l1;
#pragma unroll
        for (int nf = 0; nf < 8; nf++) {
            int col = nf * 8 + 2 * t;
            size_t row = (size_t)(qr0b + g);
            *(float2*)&out[base + row * HEAD + col] =
                make_float2(of[nf][0] * inv0, of[nf][1] * inv0);
            *(float2*)&out[base + (row + 8) * HEAD + col] =
                make_float2(of[nf][2] * inv1, of[nf][3] * inv1);
        }
    }
}

// ---------------------------------------------------------------------------
extern "C" void kernel_launch(void* const* d_in, const int* in_sizes, int n_in,
                              void* d_out, int out_size)
{
    const float* X  = (const float*)d_in[0];
    const float* Wk = (const float*)d_in[1];
    const float* Wq = (const float*)d_in[2];
    const float* Wv = (const float*)d_in[3];
    float* out = (float*)d_out;

    static bool attr_set = false;
    if (!attr_set) {
        cudaFuncSetAttribute(proj_kernel,
                             cudaFuncAttributeMaxDynamicSharedMemorySize,
                             PROJ_SMEM);
        cudaFuncSetAttribute(attn_kernel,
                             cudaFuncAttributeMaxDynamicSharedMemorySize,
                             ATTN_SMEM);
        attr_set = true;
    }

    wtrans_kernel<<<192, 384>>>(Wk, Wq, Wv);
    proj_kernel<<<(BATCH * SEQ) / 128, 512, PROJ_SMEM>>>(X);
    attn_kernel<<<BATCH, 256, ATTN_SMEM>>>(out);
}